// round 14
// baseline (speedup 1.0000x reference)
#include <cuda_runtime.h>
#include <cuda_fp16.h>
#include <cstdint>

#define L 32768
#define H 256
#define P 256
#define NC 1024
#define CHUNK 32    // L / NC

#define SST 20            // smem row stride in uints (16 data + 4 pad)
#define STG (256 * SST)   // (128 A rows + 128 B rows) * SST uints per stage
#define NSTAGE 3
#define GSMEM (NSTAGE * STG * 4)

// ---------------- device scratch (no dynamic allocation allowed) -------------
__device__ unsigned g_u_h[L * H / 2];        // u as half2 (packed along h)
__device__ unsigned g_Bcat[512 * (H / 2)];   // rows 0-255: B_bar re; 256-511: im (half2)
__device__ unsigned g_Ccat[H * 256];         // row h: [Cre(128 uints) | -Cim(128)] half2
__device__ float g_Are[P];
__device__ float g_Aim[P];
__device__ __half g_Bu_h[L * 512];           // [l][0:256]=re, [256:512]=im (half)
__device__ unsigned g_xs_h[L * 256];         // half: [l][0:256]=xr, [256:512]=xi
__device__ float4 g_agg[NC * P];             // per-chunk affine (Mr, Mi, br, bi)
__device__ float2 g_state[NC * P];           // per-chunk exit state
__device__ unsigned g_flag[NC];              // 0=none, 1=agg ready, 2=state ready

// ---------------- helpers -----------------------------------------------------
__device__ __forceinline__ unsigned packh2(float a, float b) {
    __half2 h = __floats2half2_rn(a, b);
    return *reinterpret_cast<unsigned*>(&h);
}

__device__ __forceinline__ uint32_t s2u(const void* p) {
    uint32_t a;
    asm("{ .reg .u64 t; cvta.to.shared.u64 t, %1; cvt.u32.u64 %0, t; }" : "=r"(a) : "l"(p));
    return a;
}

__device__ __forceinline__ void mma_f16(float d[4], const unsigned a[4], const unsigned b[2]) {
    asm volatile(
        "mma.sync.aligned.m16n8k16.row.col.f32.f16.f16.f32 "
        "{%0,%1,%2,%3},{%4,%5,%6,%7},{%8,%9},{%0,%1,%2,%3};"
        : "+f"(d[0]), "+f"(d[1]), "+f"(d[2]), "+f"(d[3])
        : "r"(a[0]), "r"(a[1]), "r"(a[2]), "r"(a[3]), "r"(b[0]), "r"(b[1]));
}

__device__ __forceinline__ void ldsm_x4(unsigned r[4], uint32_t addr) {
    asm volatile("ldmatrix.sync.aligned.m8n8.x4.shared.b16 {%0,%1,%2,%3}, [%4];"
        : "=r"(r[0]), "=r"(r[1]), "=r"(r[2]), "=r"(r[3]) : "r"(addr));
}

#define CP16(s, g) \
    asm volatile("cp.async.cg.shared.global [%0], [%1], 16;" :: "r"(s), "l"(g) : "memory")
#define CP_COMMIT() asm volatile("cp.async.commit_group;" ::: "memory")
#define CP_WAIT1() asm volatile("cp.async.wait_group 1;" ::: "memory")
#define CP_WAIT0() asm volatile("cp.async.wait_group 0;" ::: "memory")

// ---------------- fused prep: conv u, deint C, setup Lambda/B, clear flags ---
#define NU (L * H / 2)
#define NDC (H * P / 2)
#define NSU (P * 128)
__global__ void k_prep(const float* __restrict__ u, const float* __restrict__ Cin,
                       const float* __restrict__ Lre, const float* __restrict__ Lim,
                       const float* __restrict__ Bin, const float* __restrict__ logstep) {
    int idx = blockIdx.x * 256 + threadIdx.x;
    if (idx < NU) {
        float2 v = ((const float2*)u)[idx];
        g_u_h[idx] = packh2(v.x, v.y);
    } else if (idx < NU + NDC) {
        int i = idx - NU;
        int h = i >> 7, pp = i & 127;
        float4 v = ((const float4*)Cin)[i];
        g_Ccat[h * 256 + pp]       = packh2(v.x, v.z);
        g_Ccat[h * 256 + 128 + pp] = packh2(-v.y, -v.w);
    } else if (idx < NU + NDC + NSU) {
        int i = idx - NU - NDC;
        int p = i >> 7, h2 = i & 127;
        float lr = Lre[p], li = Lim[p];
        float dt = expf(logstep[p]);
        float e = expf(lr * dt);
        float Abr = e * cosf(li * dt);
        float Abi = e * sinf(li * dt);
        if (h2 == 0) { g_Are[p] = Abr; g_Aim[p] = Abi; }
        float nr = Abr - 1.0f, ni = Abi;
        float inv = 1.0f / (lr * lr + li * li);
        float cr = (nr * lr + ni * li) * inv;
        float ci = (ni * lr - nr * li) * inv;
        int h0 = 2 * h2;
        float b00 = Bin[(p * H + h0) * 2 + 0], b01 = Bin[(p * H + h0) * 2 + 1];
        float b10 = Bin[(p * H + h0 + 1) * 2 + 0], b11 = Bin[(p * H + h0 + 1) * 2 + 1];
        g_Bcat[p * (H / 2) + h2]       = packh2(cr * b00 - ci * b01, cr * b10 - ci * b11);
        g_Bcat[(P + p) * (H / 2) + h2] = packh2(cr * b01 + ci * b00, cr * b11 + ci * b10);
    } else if (idx < NU + NDC + NSU + NC) {
        g_flag[idx - NU - NDC - NSU] = 0u;
    }
}

// ---------------- fp16 GEMM (R10 best): M=128 N=128, 3-stage cp.async ring ----
template<int KH2, bool EPI_Y>
__global__ __launch_bounds__(256, 2) void k_gemm(const unsigned* __restrict__ Ag,
                                                 const unsigned* __restrict__ Bg,
                                                 void* __restrict__ Cout, int ldc,
                                                 const float* __restrict__ u,
                                                 const float* __restrict__ Dv) {
    constexpr int KITER = KH2 / 16;
    extern __shared__ unsigned sm[];
    const uint32_t sb = s2u(sm);
    const int tid = threadIdx.x, lane = tid & 31, wid = tid >> 5;
    const int bm = blockIdx.x * 128, bn = blockIdx.y * 128;
    const int wr = (wid & 1) * 64, wc = (wid >> 1) * 32;

    const int lr0 = tid >> 2, lc = (tid & 3) * 4;
    const unsigned* gA0 = Ag + (size_t)(bm + lr0) * KH2 + lc;
    const unsigned* gA1 = gA0 + (size_t)64 * KH2;
    const unsigned* gB0 = Bg + (size_t)(bn + lr0) * KH2 + lc;
    const unsigned* gB1 = gB0 + (size_t)64 * KH2;
    const uint32_t dA0 = sb + (lr0 * SST + lc) * 4;
    const uint32_t dA1 = sb + ((lr0 + 64) * SST + lc) * 4;
    const uint32_t dB0 = sb + ((128 + lr0) * SST + lc) * 4;
    const uint32_t dB1 = sb + ((192 + lr0) * SST + lc) * 4;

    const uint32_t aoff = ((wr + (lane & 15)) * SST + ((lane >> 4) << 2)) * 4;
    const int lg = lane >> 3;
    const uint32_t boff = ((128 + wc + (lg & 2) * 4 + (lane & 7)) * SST + ((lg & 1) << 2)) * 4;

    float acc[4][4][4] = {};

#define PF(c) do { int k0 = (c) * 16; uint32_t bo = ((c) % NSTAGE) * (STG * 4); \
        CP16(dA0 + bo, gA0 + k0); CP16(dA1 + bo, gA1 + k0); \
        CP16(dB0 + bo, gB0 + k0); CP16(dB1 + bo, gB1 + k0); \
        CP_COMMIT(); } while (0)

    PF(0);
    PF(1);
#pragma unroll 1
    for (int c = 0; c < KITER; c++) {
        if (c == KITER - 1) { CP_WAIT0(); } else { CP_WAIT1(); }
        __syncthreads();
        if (c + NSTAGE - 1 < KITER) PF(c + NSTAGE - 1);
        const uint32_t Sb = sb + (c % NSTAGE) * (STG * 4);
#pragma unroll
        for (int ko = 0; ko < 16; ko += 8) {
            unsigned af[4][4];
#pragma unroll
            for (int mt = 0; mt < 4; mt++)
                ldsm_x4(af[mt], Sb + aoff + (mt * 16 * SST + ko) * 4);
#pragma unroll
            for (int nt2 = 0; nt2 < 2; nt2++) {
                unsigned bf[4];
                ldsm_x4(bf, Sb + boff + (nt2 * 16 * SST + ko) * 4);
#pragma unroll
                for (int mt = 0; mt < 4; mt++) {
                    mma_f16(acc[mt][2 * nt2],     af[mt], bf);
                    mma_f16(acc[mt][2 * nt2 + 1], af[mt], bf + 2);
                }
            }
        }
    }
#undef PF

    const int gp = lane >> 2, tg = lane & 3;
#pragma unroll
    for (int mt = 0; mt < 4; mt++)
#pragma unroll
        for (int nt = 0; nt < 4; nt++) {
            int row = bm + wr + mt * 16 + gp;
            int col = bn + wc + nt * 8 + 2 * tg;
            if (EPI_Y) {
                float* outf = (float*)Cout;
                float2 dv = *(const float2*)&Dv[col];
                float2 u0 = *(const float2*)&u[(size_t)row * H + col];
                float2 u1 = *(const float2*)&u[(size_t)(row + 8) * H + col];
                float2 o0 = make_float2(2.0f * acc[mt][nt][0] + u0.x * dv.x,
                                        2.0f * acc[mt][nt][1] + u0.y * dv.y);
                float2 o1 = make_float2(2.0f * acc[mt][nt][2] + u1.x * dv.x,
                                        2.0f * acc[mt][nt][3] + u1.y * dv.y);
                *(float2*)&outf[(size_t)row * ldc + col]       = o0;
                *(float2*)&outf[(size_t)(row + 8) * ldc + col] = o1;
            } else {
                __half* outh = (__half*)Cout;
                *(__half2*)&outh[(size_t)row * ldc + col] =
                    __floats2half2_rn(acc[mt][nt][0], acc[mt][nt][1]);
                *(__half2*)&outh[(size_t)(row + 8) * ldc + col] =
                    __floats2half2_rn(acc[mt][nt][2], acc[mt][nt][3]);
            }
        }
}

// ---------------- fused single-pass scan (decoupled lookback) ----------------
// 1024 blocks; block c owns chunk c (32 steps), thread p owns channel p.
__global__ __launch_bounds__(256) void k_scan(const unsigned int* __restrict__ start,
                                              const float* __restrict__ hidden,
                                              float* __restrict__ out, int fmt) {
    __shared__ unsigned sflag;
    const int c = blockIdx.x, p = threadIdx.x;
    const int l0 = c * CHUNK;
    const float Ar = g_Are[p], Ai = g_Aim[p];

    // load chunk inputs into registers
    float br[CHUNK], bi[CHUNK];
#pragma unroll
    for (int t = 0; t < CHUNK; t++) {
        int l = l0 + t;
        br[t] = __half2float(g_Bu_h[(size_t)l * 512 + p]);
        bi[t] = __half2float(g_Bu_h[(size_t)l * 512 + 256 + p]);
    }
    unsigned v = start[l0 + (p & 31)];
    unsigned smask = __ballot_sync(0xffffffffu, v != 0u);

    // local affine aggregate over the chunk (resets embedded)
    float Mr = 1.0f, Mi = 0.0f, xr = 0.0f, xi = 0.0f;
#pragma unroll
    for (int t = 0; t < CHUNK; t++) {
        bool s = (smask >> t) & 1u;
        float pr = s ? 0.0f : xr, pi = s ? 0.0f : xi;
        float mr = s ? 0.0f : Mr, mi = s ? 0.0f : Mi;
        xr = Ar * pr - Ai * pi + br[t];
        xi = Ar * pi + Ai * pr + bi[t];
        Mr = Ar * mr - Ai * mi;
        Mi = Ar * mi + Ai * mr;
    }

    // publish aggregate (flag 1)
    if (c > 0) {
        g_agg[c * P + p] = make_float4(Mr, Mi, xr, xi);
        __threadfence();
        __syncthreads();
        if (p == 0) atomicExch(&g_flag[c], 1u);
    }

    // lookback: compute entry state (er, ei)
    float er, ei;
    if (c == 0) {
        er = hidden[p]; ei = 0.0f;
    } else {
        float EMr = 1.0f, EMi = 0.0f, Ebr = 0.0f, Ebi = 0.0f;
        int j = c - 1;
        for (;;) {
            if (p == 0) {
                unsigned f;
                do { f = *(volatile unsigned*)&g_flag[j]; } while (f == 0u);
                sflag = f;
            }
            __syncthreads();
            unsigned f = sflag;
            __syncthreads();
            __threadfence();
            if (f == 2u) {
                float2 s = g_state[j * P + p];
                er = EMr * s.x - EMi * s.y + Ebr;
                ei = EMr * s.y + EMi * s.x + Ebi;
                break;
            }
            float4 a = g_agg[j * P + p];
            float nMr = EMr * a.x - EMi * a.y;
            float nMi = EMr * a.y + EMi * a.x;
            float nbr = EMr * a.z - EMi * a.w + Ebr;
            float nbi = EMr * a.w + EMi * a.z + Ebi;
            EMr = nMr; EMi = nMi; Ebr = nbr; Ebi = nbi;
            if (--j < 0) {
                float hr = hidden[p];
                er = EMr * hr + Ebr;
                ei = EMi * hr + Ebi;
                break;
            }
        }
    }

    // publish exit state (flag 2)
    float exr = Mr * er - Mi * ei + xr;
    float exi = Mr * ei + Mi * er + xi;
    g_state[c * P + p] = make_float2(exr, exi);
    __threadfence();
    __syncthreads();
    if (p == 0) atomicExch(&g_flag[c], 2u);

    // re-scan from entry state, write xs (half)
    __half* xs = (__half*)g_xs_h;
    float vr2 = er, vi2 = ei;
#pragma unroll
    for (int t = 0; t < CHUNK; t++) {
        bool s = (smask >> t) & 1u;
        float pr = s ? 0.0f : vr2, pi = s ? 0.0f : vi2;
        vr2 = Ar * pr - Ai * pi + br[t];
        vi2 = Ar * pi + Ai * pr + bi[t];
        int l = l0 + t;
        xs[(size_t)l * 512 + p]       = __float2half_rn(vr2);
        xs[(size_t)l * 512 + 256 + p] = __float2half_rn(vi2);
    }
    if (c == NC - 1) {
        if (fmt == 2) { out[2 * p] = vr2; out[2 * p + 1] = vi2; }
        else if (fmt == 1) { out[p] = vr2; }
    }
}

// ---------------- launcher ---------------------------------------------------
extern "C" void kernel_launch(void* const* d_in, const int* in_sizes, int n_in,
                              void* d_out, int out_size) {
    const float* Lre    = (const float*)d_in[0];
    const float* Lim    = (const float*)d_in[1];
    const float* Bin    = (const float*)d_in[2];
    const float* Cin    = (const float*)d_in[3];
    const float* lstep  = (const float*)d_in[4];
    const float* D      = (const float*)d_in[5];
    const float* hidden = (const float*)d_in[6];
    const float* u      = (const float*)d_in[7];
    const unsigned int* start = (const unsigned int*)d_in[8];
    float* out = (float*)d_out;

    int state_floats = out_size - L * H;
    if (state_floats < 0) state_floats = 0;
    int fmt = (state_floats >= 2 * P) ? 2 : (state_floats >= P ? 1 : 0);
    float* ys = out + state_floats;

    cudaFuncSetAttribute(k_gemm<128, false>, cudaFuncAttributeMaxDynamicSharedMemorySize, GSMEM);
    cudaFuncSetAttribute(k_gemm<256, true>,  cudaFuncAttributeMaxDynamicSharedMemorySize, GSMEM);

    int prep_blocks = (NU + NDC + NSU + NC + 255) / 256;
    k_prep<<<prep_blocks, 256>>>(u, Cin, Lre, Lim, Bin, lstep);

    // GEMM1: Bu_h[l, 0:512] = u @ [Bre; Bim]^T   (K = 256 halves = 128 uints)
    {
        void *bu_dev = nullptr, *a_dev = nullptr, *b_dev = nullptr;
        cudaGetSymbolAddress(&bu_dev, g_Bu_h);
        cudaGetSymbolAddress(&a_dev, g_u_h);
        cudaGetSymbolAddress(&b_dev, g_Bcat);
        dim3 g(L / 128, 512 / 128);
        k_gemm<128, false><<<g, 256, GSMEM>>>((const unsigned*)a_dev, (const unsigned*)b_dev,
                                              bu_dev, 512, nullptr, nullptr);
    }

    // fused single-pass segmented scan (scan1 + scan2 + scan3)
    k_scan<<<NC, P>>>(start, hidden, out, fmt);

    // GEMM2: ys = 2 * (xs_cat @ Ccat^T) + u * D   (K = 512 halves = 256 uints)
    {
        void *a_dev = nullptr, *b_dev = nullptr;
        cudaGetSymbolAddress(&a_dev, g_xs_h);
        cudaGetSymbolAddress(&b_dev, g_Ccat);
        dim3 g(L / 128, H / 128);
        k_gemm<256, true><<<g, 256, GSMEM>>>((const unsigned*)a_dev, (const unsigned*)b_dev,
                                             ys, H, u, D);
    }
}

// round 15
// speedup vs baseline: 1.4015x; 1.4015x over previous
#include <cuda_runtime.h>
#include <cuda_fp16.h>
#include <cstdint>

#define L 32768
#define H 256
#define P 256
#define NC 1024
#define CHUNK 32    // L / NC
#define NG 128      // groups (NC / NG = 8 chunks per group)
#define CPG 8       // chunks per group

#define SST 20            // smem row stride in uints (16 data + 4 pad)
#define STG (256 * SST)   // (128 A rows + 128 B rows) * SST uints per stage
#define NSTAGE 3
#define GSMEM (NSTAGE * STG * 4)

// ---------------- device scratch (no dynamic allocation allowed) -------------
__device__ unsigned g_u_h[L * H / 2];        // u as half2 (packed along h)
__device__ unsigned g_Bcat[512 * (H / 2)];   // rows 0-255: B_bar re; 256-511: im (half2)
__device__ unsigned g_Ccat[H * 256];         // row h: [Cre(128 uints) | -Cim(128)] half2
__device__ float g_Are[P];
__device__ float g_Aim[P];
__device__ __half g_Bu_h[L * 512];           // [l][0:256]=re, [256:512]=im (half)
__device__ unsigned g_xs_h[L * 256];         // half: [l][0:256]=xr, [256:512]=xi
__device__ float g_Mre[NC * P], g_Mim[NC * P];
__device__ float g_bre[NC * P], g_bim[NC * P];
__device__ float g_gMr[NG * P], g_gMi[NG * P];   // group aggregates
__device__ float g_gbr[NG * P], g_gbi[NG * P];
__device__ float g_xgr[NG * P], g_xgi[NG * P];   // group-entry states

// ---------------- helpers -----------------------------------------------------
__device__ __forceinline__ unsigned packh2(float a, float b) {
    __half2 h = __floats2half2_rn(a, b);
    return *reinterpret_cast<unsigned*>(&h);
}

__device__ __forceinline__ uint32_t s2u(const void* p) {
    uint32_t a;
    asm("{ .reg .u64 t; cvta.to.shared.u64 t, %1; cvt.u32.u64 %0, t; }" : "=r"(a) : "l"(p));
    return a;
}

__device__ __forceinline__ void mma_f16(float d[4], const unsigned a[4], const unsigned b[2]) {
    asm volatile(
        "mma.sync.aligned.m16n8k16.row.col.f32.f16.f16.f32 "
        "{%0,%1,%2,%3},{%4,%5,%6,%7},{%8,%9},{%0,%1,%2,%3};"
        : "+f"(d[0]), "+f"(d[1]), "+f"(d[2]), "+f"(d[3])
        : "r"(a[0]), "r"(a[1]), "r"(a[2]), "r"(a[3]), "r"(b[0]), "r"(b[1]));
}

__device__ __forceinline__ void ldsm_x4(unsigned r[4], uint32_t addr) {
    asm volatile("ldmatrix.sync.aligned.m8n8.x4.shared.b16 {%0,%1,%2,%3}, [%4];"
        : "=r"(r[0]), "=r"(r[1]), "=r"(r[2]), "=r"(r[3]) : "r"(addr));
}

#define CP16(s, g) \
    asm volatile("cp.async.cg.shared.global [%0], [%1], 16;" :: "r"(s), "l"(g) : "memory")
#define CP_COMMIT() asm volatile("cp.async.commit_group;" ::: "memory")
#define CP_WAIT1() asm volatile("cp.async.wait_group 1;" ::: "memory")
#define CP_WAIT0() asm volatile("cp.async.wait_group 0;" ::: "memory")

// ---------------- fused prep: conv u, deint C, setup Lambda/B ----------------
#define NU (L * H / 2)
#define NDC (H * P / 2)
#define NSU (P * 128)
__global__ void k_prep(const float* __restrict__ u, const float* __restrict__ Cin,
                       const float* __restrict__ Lre, const float* __restrict__ Lim,
                       const float* __restrict__ Bin, const float* __restrict__ logstep) {
    int idx = blockIdx.x * 256 + threadIdx.x;
    if (idx < NU) {
        float2 v = ((const float2*)u)[idx];
        g_u_h[idx] = packh2(v.x, v.y);
    } else if (idx < NU + NDC) {
        int i = idx - NU;
        int h = i >> 7, pp = i & 127;
        float4 v = ((const float4*)Cin)[i];
        g_Ccat[h * 256 + pp]       = packh2(v.x, v.z);
        g_Ccat[h * 256 + 128 + pp] = packh2(-v.y, -v.w);
    } else if (idx < NU + NDC + NSU) {
        int i = idx - NU - NDC;
        int p = i >> 7, h2 = i & 127;
        float lr = Lre[p], li = Lim[p];
        float dt = expf(logstep[p]);
        float e = expf(lr * dt);
        float Abr = e * cosf(li * dt);
        float Abi = e * sinf(li * dt);
        if (h2 == 0) { g_Are[p] = Abr; g_Aim[p] = Abi; }
        float nr = Abr - 1.0f, ni = Abi;
        float inv = 1.0f / (lr * lr + li * li);
        float cr = (nr * lr + ni * li) * inv;
        float ci = (ni * lr - nr * li) * inv;
        int h0 = 2 * h2;
        float b00 = Bin[(p * H + h0) * 2 + 0], b01 = Bin[(p * H + h0) * 2 + 1];
        float b10 = Bin[(p * H + h0 + 1) * 2 + 0], b11 = Bin[(p * H + h0 + 1) * 2 + 1];
        g_Bcat[p * (H / 2) + h2]       = packh2(cr * b00 - ci * b01, cr * b10 - ci * b11);
        g_Bcat[(P + p) * (H / 2) + h2] = packh2(cr * b01 + ci * b00, cr * b11 + ci * b10);
    }
}

// ---------------- fp16 GEMM (R10 best): M=128 N=128, 3-stage cp.async ring ----
// EPI_Y epilogue reads u as half2 (g_u_h) and D as fp32.
template<int KH2, bool EPI_Y>
__global__ __launch_bounds__(256, 2) void k_gemm(const unsigned* __restrict__ Ag,
                                                 const unsigned* __restrict__ Bg,
                                                 void* __restrict__ Cout, int ldc,
                                                 const unsigned* __restrict__ uh,
                                                 const float* __restrict__ Dv) {
    constexpr int KITER = KH2 / 16;
    extern __shared__ unsigned sm[];
    const uint32_t sb = s2u(sm);
    const int tid = threadIdx.x, lane = tid & 31, wid = tid >> 5;
    const int bm = blockIdx.x * 128, bn = blockIdx.y * 128;
    const int wr = (wid & 1) * 64, wc = (wid >> 1) * 32;

    const int lr0 = tid >> 2, lc = (tid & 3) * 4;
    const unsigned* gA0 = Ag + (size_t)(bm + lr0) * KH2 + lc;
    const unsigned* gA1 = gA0 + (size_t)64 * KH2;
    const unsigned* gB0 = Bg + (size_t)(bn + lr0) * KH2 + lc;
    const unsigned* gB1 = gB0 + (size_t)64 * KH2;
    const uint32_t dA0 = sb + (lr0 * SST + lc) * 4;
    const uint32_t dA1 = sb + ((lr0 + 64) * SST + lc) * 4;
    const uint32_t dB0 = sb + ((128 + lr0) * SST + lc) * 4;
    const uint32_t dB1 = sb + ((192 + lr0) * SST + lc) * 4;

    const uint32_t aoff = ((wr + (lane & 15)) * SST + ((lane >> 4) << 2)) * 4;
    const int lg = lane >> 3;
    const uint32_t boff = ((128 + wc + (lg & 2) * 4 + (lane & 7)) * SST + ((lg & 1) << 2)) * 4;

    float acc[4][4][4] = {};

#define PF(c) do { int k0 = (c) * 16; uint32_t bo = ((c) % NSTAGE) * (STG * 4); \
        CP16(dA0 + bo, gA0 + k0); CP16(dA1 + bo, gA1 + k0); \
        CP16(dB0 + bo, gB0 + k0); CP16(dB1 + bo, gB1 + k0); \
        CP_COMMIT(); } while (0)

    PF(0);
    PF(1);
#pragma unroll 1
    for (int c = 0; c < KITER; c++) {
        if (c == KITER - 1) { CP_WAIT0(); } else { CP_WAIT1(); }
        __syncthreads();
        if (c + NSTAGE - 1 < KITER) PF(c + NSTAGE - 1);
        const uint32_t Sb = sb + (c % NSTAGE) * (STG * 4);
#pragma unroll
        for (int ko = 0; ko < 16; ko += 8) {
            unsigned af[4][4];
#pragma unroll
            for (int mt = 0; mt < 4; mt++)
                ldsm_x4(af[mt], Sb + aoff + (mt * 16 * SST + ko) * 4);
#pragma unroll
            for (int nt2 = 0; nt2 < 2; nt2++) {
                unsigned bf[4];
                ldsm_x4(bf, Sb + boff + (nt2 * 16 * SST + ko) * 4);
#pragma unroll
                for (int mt = 0; mt < 4; mt++) {
                    mma_f16(acc[mt][2 * nt2],     af[mt], bf);
                    mma_f16(acc[mt][2 * nt2 + 1], af[mt], bf + 2);
                }
            }
        }
    }
#undef PF

    const int gp = lane >> 2, tg = lane & 3;
#pragma unroll
    for (int mt = 0; mt < 4; mt++)
#pragma unroll
        for (int nt = 0; nt < 4; nt++) {
            int row = bm + wr + mt * 16 + gp;
            int col = bn + wc + nt * 8 + 2 * tg;
            if (EPI_Y) {
                float* outf = (float*)Cout;
                float2 dv = *(const float2*)&Dv[col];
                unsigned uw0 = uh[(size_t)row * (H / 2) + (col >> 1)];
                unsigned uw1 = uh[(size_t)(row + 8) * (H / 2) + (col >> 1)];
                float2 u0 = __half22float2(*reinterpret_cast<__half2*>(&uw0));
                float2 u1 = __half22float2(*reinterpret_cast<__half2*>(&uw1));
                float2 o0 = make_float2(2.0f * acc[mt][nt][0] + u0.x * dv.x,
                                        2.0f * acc[mt][nt][1] + u0.y * dv.y);
                float2 o1 = make_float2(2.0f * acc[mt][nt][2] + u1.x * dv.x,
                                        2.0f * acc[mt][nt][3] + u1.y * dv.y);
                *(float2*)&outf[(size_t)row * ldc + col]       = o0;
                *(float2*)&outf[(size_t)(row + 8) * ldc + col] = o1;
            } else {
                __half* outh = (__half*)Cout;
                *(__half2*)&outh[(size_t)row * ldc + col] =
                    __floats2half2_rn(acc[mt][nt][0], acc[mt][nt][1]);
                *(__half2*)&outh[(size_t)(row + 8) * ldc + col] =
                    __floats2half2_rn(acc[mt][nt][2], acc[mt][nt][3]);
            }
        }
}

// ---------------- scan phase 1: per-chunk affine aggregates ------------------
__global__ __launch_bounds__(256) void k_scan1(const unsigned int* __restrict__ start) {
    int c = blockIdx.x, p = threadIdx.x;
    int l0 = c * CHUNK;
    float Ar = g_Are[p], Ai = g_Aim[p];
    float Mr = 1.0f, Mi = 0.0f, xr = 0.0f, xi = 0.0f;
#pragma unroll 8
    for (int t = 0; t < CHUNK; t++) {
        int l = l0 + t;
        float br = __half2float(g_Bu_h[(size_t)l * 512 + p]);
        float bi = __half2float(g_Bu_h[(size_t)l * 512 + 256 + p]);
        bool s = (start[l] != 0u);
        float pr = s ? 0.0f : xr, pi = s ? 0.0f : xi;
        float mr = s ? 0.0f : Mr, mi = s ? 0.0f : Mi;
        xr = Ar * pr - Ai * pi + br;
        xi = Ar * pi + Ai * pr + bi;
        Mr = Ar * mr - Ai * mi;
        Mi = Ar * mi + Ai * mr;
    }
    g_Mre[c * P + p] = Mr; g_Mim[c * P + p] = Mi;
    g_bre[c * P + p] = xr; g_bim[c * P + p] = xi;
}

// ---------------- scan phase 2a: group aggregates (8 chunks/group) -----------
__global__ __launch_bounds__(256) void k_scan2a() {
    int g = blockIdx.x, p = threadIdx.x;
    int c0 = g * CPG;
    float mr[CPG], mi[CPG], vr[CPG], vi[CPG];
#pragma unroll
    for (int j = 0; j < CPG; j++) {
        int a = (c0 + j) * P + p;
        mr[j] = g_Mre[a]; mi[j] = g_Mim[a]; vr[j] = g_bre[a]; vi[j] = g_bim[a];
    }
    float Mr = mr[0], Mi = mi[0], br = vr[0], bi = vi[0];
#pragma unroll
    for (int j = 1; j < CPG; j++) {
        float tMr = mr[j] * Mr - mi[j] * Mi;
        float tMi = mr[j] * Mi + mi[j] * Mr;
        float tbr = mr[j] * br - mi[j] * bi + vr[j];
        float tbi = mr[j] * bi + mi[j] * br + vi[j];
        Mr = tMr; Mi = tMi; br = tbr; bi = tbi;
    }
    g_gMr[g * P + p] = Mr; g_gMi[g * P + p] = Mi;
    g_gbr[g * P + p] = br; g_gbi[g * P + p] = bi;
}

// ---------------- scan phase 2b: serial prefix over NG groups (depth-8 PF) ---
__global__ __launch_bounds__(256) void k_scan2b(const float* __restrict__ hidden) {
    int p = threadIdx.x;
    float bmr[8], bmi[8], bvr[8], bvi[8];
#pragma unroll
    for (int k = 0; k < 8; k++) {
        int a = k * P + p;
        bmr[k] = g_gMr[a]; bmi[k] = g_gMi[a]; bvr[k] = g_gbr[a]; bvi[k] = g_gbi[a];
    }
    float xr = hidden[p], xi = 0.0f;
#pragma unroll
    for (int g = 0; g < NG; g++) {
        int s = g & 7;
        float mr = bmr[s], mi = bmi[s], vr = bvr[s], vi = bvi[s];
        if (g + 8 < NG) {
            int a = (g + 8) * P + p;
            bmr[s] = g_gMr[a]; bmi[s] = g_gMi[a]; bvr[s] = g_gbr[a]; bvi[s] = g_gbi[a];
        }
        g_xgr[g * P + p] = xr; g_xgi[g * P + p] = xi;
        float nr = mr * xr - mi * xi + vr;
        float ni = mr * xi + mi * xr + vi;
        xr = nr; xi = ni;
    }
}

// ---------------- scan phase 3: fused expand + re-scan + final state ---------
__global__ __launch_bounds__(256) void k_scan3(const unsigned int* __restrict__ start,
                                               float* __restrict__ out, int fmt) {
    int c = blockIdx.x, p = threadIdx.x;
    int g = c >> 3;                         // group index (CPG = 8)
    float xr = g_xgr[g * P + p], xi = g_xgi[g * P + p];

    // compose intra-group chunk aggregates before chunk c (loads batched first)
    int n = c - (g << 3);
    float mr[CPG - 1], mi[CPG - 1], vr[CPG - 1], vi[CPG - 1];
    for (int j = 0; j < n; j++) {
        int a = ((g << 3) + j) * P + p;
        mr[j] = g_Mre[a]; mi[j] = g_Mim[a]; vr[j] = g_bre[a]; vi[j] = g_bim[a];
    }
    for (int j = 0; j < n; j++) {
        float nr = mr[j] * xr - mi[j] * xi + vr[j];
        float ni = mr[j] * xi + mi[j] * xr + vi[j];
        xr = nr; xi = ni;
    }

    float Ar = g_Are[p], Ai = g_Aim[p];
    int l0 = c * CHUNK;
    __half* xs = (__half*)g_xs_h;
#pragma unroll 8
    for (int t = 0; t < CHUNK; t++) {
        int l = l0 + t;
        float br = __half2float(g_Bu_h[(size_t)l * 512 + p]);
        float bi = __half2float(g_Bu_h[(size_t)l * 512 + 256 + p]);
        bool s = (start[l] != 0u);
        float pr = s ? 0.0f : xr, pi = s ? 0.0f : xi;
        xr = Ar * pr - Ai * pi + br;
        xi = Ar * pi + Ai * pr + bi;
        xs[(size_t)l * 512 + p]       = __float2half_rn(xr);
        xs[(size_t)l * 512 + 256 + p] = __float2half_rn(xi);
    }
    if (c == NC - 1) {
        if (fmt == 2) { out[2 * p] = xr; out[2 * p + 1] = xi; }
        else if (fmt == 1) { out[p] = xr; }
    }
}

// ---------------- launcher ---------------------------------------------------
extern "C" void kernel_launch(void* const* d_in, const int* in_sizes, int n_in,
                              void* d_out, int out_size) {
    const float* Lre    = (const float*)d_in[0];
    const float* Lim    = (const float*)d_in[1];
    const float* Bin    = (const float*)d_in[2];
    const float* Cin    = (const float*)d_in[3];
    const float* lstep  = (const float*)d_in[4];
    const float* D      = (const float*)d_in[5];
    const float* hidden = (const float*)d_in[6];
    const float* u      = (const float*)d_in[7];
    const unsigned int* start = (const unsigned int*)d_in[8];
    float* out = (float*)d_out;

    int state_floats = out_size - L * H;
    if (state_floats < 0) state_floats = 0;
    int fmt = (state_floats >= 2 * P) ? 2 : (state_floats >= P ? 1 : 0);
    float* ys = out + state_floats;

    cudaFuncSetAttribute(k_gemm<128, false>, cudaFuncAttributeMaxDynamicSharedMemorySize, GSMEM);
    cudaFuncSetAttribute(k_gemm<256, true>,  cudaFuncAttributeMaxDynamicSharedMemorySize, GSMEM);

    int prep_blocks = (NU + NDC + NSU + 255) / 256;
    k_prep<<<prep_blocks, 256>>>(u, Cin, Lre, Lim, Bin, lstep);

    // GEMM1: Bu_h[l, 0:512] = u @ [Bre; Bim]^T   (K = 256 halves = 128 uints)
    {
        void *bu_dev = nullptr, *a_dev = nullptr, *b_dev = nullptr;
        cudaGetSymbolAddress(&bu_dev, g_Bu_h);
        cudaGetSymbolAddress(&a_dev, g_u_h);
        cudaGetSymbolAddress(&b_dev, g_Bcat);
        dim3 g(L / 128, 512 / 128);
        k_gemm<128, false><<<g, 256, GSMEM>>>((const unsigned*)a_dev, (const unsigned*)b_dev,
                                              bu_dev, 512, nullptr, nullptr);
    }

    k_scan1<<<NC, P>>>(start);
    k_scan2a<<<NG, P>>>();
    k_scan2b<<<1, P>>>(hidden);
    k_scan3<<<NC, P>>>(start, out, fmt);

    // GEMM2: ys = 2 * (xs_cat @ Ccat^T) + u * D   (K = 512 halves = 256 uints)
    {
        void *a_dev = nullptr, *b_dev = nullptr, *uh_dev = nullptr;
        cudaGetSymbolAddress(&a_dev, g_xs_h);
        cudaGetSymbolAddress(&b_dev, g_Ccat);
        cudaGetSymbolAddress(&uh_dev, g_u_h);
        dim3 g(L / 128, H / 128);
        k_gemm<256, true><<<g, 256, GSMEM>>>((const unsigned*)a_dev, (const unsigned*)b_dev,
                                             ys, H, (const unsigned*)uh_dev, D);
    }
}

// round 16
// speedup vs baseline: 1.5065x; 1.0749x over previous
#include <cuda_runtime.h>
#include <cuda_fp16.h>
#include <cstdint>

#define L 32768
#define H 256
#define P 256
#define NC 1024
#define CHUNK 32    // L / NC
#define NG 128      // groups (NC / NG = 8 chunks per group)
#define CPG 8       // chunks per group

#define SST 20            // smem row stride in uints (16 data + 4 pad)
#define STG (256 * SST)   // (128 A rows + 128 B rows) * SST uints per stage
#define NSTAGE 3
#define GSMEM (NSTAGE * STG * 4)

// ---------------- device scratch (no dynamic allocation allowed) -------------
__device__ unsigned g_u_h[L * H / 2];        // u as half2 (packed along h)
__device__ unsigned g_Bcat[512 * (H / 2)];   // rows 0-255: B_bar re; 256-511: im (half2)
__device__ unsigned g_Ccat[H * 256];         // row h: [Cre(128 uints) | -Cim(128)] half2
__device__ float g_Are[P];
__device__ float g_Aim[P];
__device__ __half g_Bu_h[L * 512];           // [l][0:256]=re, [256:512]=im (half)
__device__ unsigned g_xs_h[L * 256];         // half: [l][0:256]=xr, [256:512]=xi
__device__ float g_Mre[NC * P], g_Mim[NC * P];
__device__ float g_bre[NC * P], g_bim[NC * P];
__device__ float g_x0re[NC * P], g_x0im[NC * P];
__device__ float g_gMr[NG * P], g_gMi[NG * P];   // group aggregates
__device__ float g_gbr[NG * P], g_gbi[NG * P];
__device__ float g_xgr[NG * P], g_xgi[NG * P];   // group-entry states

// ---------------- helpers -----------------------------------------------------
__device__ __forceinline__ unsigned packh2(float a, float b) {
    __half2 h = __floats2half2_rn(a, b);
    return *reinterpret_cast<unsigned*>(&h);
}

__device__ __forceinline__ uint32_t s2u(const void* p) {
    uint32_t a;
    asm("{ .reg .u64 t; cvta.to.shared.u64 t, %1; cvt.u32.u64 %0, t; }" : "=r"(a) : "l"(p));
    return a;
}

__device__ __forceinline__ void mma_f16(float d[4], const unsigned a[4], const unsigned b[2]) {
    asm volatile(
        "mma.sync.aligned.m16n8k16.row.col.f32.f16.f16.f32 "
        "{%0,%1,%2,%3},{%4,%5,%6,%7},{%8,%9},{%0,%1,%2,%3};"
        : "+f"(d[0]), "+f"(d[1]), "+f"(d[2]), "+f"(d[3])
        : "r"(a[0]), "r"(a[1]), "r"(a[2]), "r"(a[3]), "r"(b[0]), "r"(b[1]));
}

__device__ __forceinline__ void ldsm_x4(unsigned r[4], uint32_t addr) {
    asm volatile("ldmatrix.sync.aligned.m8n8.x4.shared.b16 {%0,%1,%2,%3}, [%4];"
        : "=r"(r[0]), "=r"(r[1]), "=r"(r[2]), "=r"(r[3]) : "r"(addr));
}

#define CP16(s, g) \
    asm volatile("cp.async.cg.shared.global [%0], [%1], 16;" :: "r"(s), "l"(g) : "memory")
#define CP_COMMIT() asm volatile("cp.async.commit_group;" ::: "memory")
#define CP_WAIT1() asm volatile("cp.async.wait_group 1;" ::: "memory")
#define CP_WAIT0() asm volatile("cp.async.wait_group 0;" ::: "memory")

// ---------------- fused prep: conv u, deint C, setup Lambda/B ----------------
#define NU (L * H / 2)
#define NDC (H * P / 2)
#define NSU (P * 128)
__global__ void k_prep(const float* __restrict__ u, const float* __restrict__ Cin,
                       const float* __restrict__ Lre, const float* __restrict__ Lim,
                       const float* __restrict__ Bin, const float* __restrict__ logstep) {
    int idx = blockIdx.x * 256 + threadIdx.x;
    if (idx < NU) {
        float2 v = ((const float2*)u)[idx];
        g_u_h[idx] = packh2(v.x, v.y);
    } else if (idx < NU + NDC) {
        int i = idx - NU;
        int h = i >> 7, pp = i & 127;
        float4 v = ((const float4*)Cin)[i];
        g_Ccat[h * 256 + pp]       = packh2(v.x, v.z);
        g_Ccat[h * 256 + 128 + pp] = packh2(-v.y, -v.w);
    } else if (idx < NU + NDC + NSU) {
        int i = idx - NU - NDC;
        int p = i >> 7, h2 = i & 127;
        float lr = Lre[p], li = Lim[p];
        float dt = expf(logstep[p]);
        float e = expf(lr * dt);
        float Abr = e * cosf(li * dt);
        float Abi = e * sinf(li * dt);
        if (h2 == 0) { g_Are[p] = Abr; g_Aim[p] = Abi; }
        float nr = Abr - 1.0f, ni = Abi;
        float inv = 1.0f / (lr * lr + li * li);
        float cr = (nr * lr + ni * li) * inv;
        float ci = (ni * lr - nr * li) * inv;
        int h0 = 2 * h2;
        float b00 = Bin[(p * H + h0) * 2 + 0], b01 = Bin[(p * H + h0) * 2 + 1];
        float b10 = Bin[(p * H + h0 + 1) * 2 + 0], b11 = Bin[(p * H + h0 + 1) * 2 + 1];
        g_Bcat[p * (H / 2) + h2]       = packh2(cr * b00 - ci * b01, cr * b10 - ci * b11);
        g_Bcat[(P + p) * (H / 2) + h2] = packh2(cr * b01 + ci * b00, cr * b11 + ci * b10);
    }
}

// ---------------- fp16 GEMM (R10 best): M=128 N=128, 3-stage cp.async ring ----
template<int KH2, bool EPI_Y>
__global__ __launch_bounds__(256, 2) void k_gemm(const unsigned* __restrict__ Ag,
                                                 const unsigned* __restrict__ Bg,
                                                 void* __restrict__ Cout, int ldc,
                                                 const float* __restrict__ u,
                                                 const float* __restrict__ Dv) {
    constexpr int KITER = KH2 / 16;
    extern __shared__ unsigned sm[];
    const uint32_t sb = s2u(sm);
    const int tid = threadIdx.x, lane = tid & 31, wid = tid >> 5;
    const int bm = blockIdx.x * 128, bn = blockIdx.y * 128;
    const int wr = (wid & 1) * 64, wc = (wid >> 1) * 32;

    const int lr0 = tid >> 2, lc = (tid & 3) * 4;
    const unsigned* gA0 = Ag + (size_t)(bm + lr0) * KH2 + lc;
    const unsigned* gA1 = gA0 + (size_t)64 * KH2;
    const unsigned* gB0 = Bg + (size_t)(bn + lr0) * KH2 + lc;
    const unsigned* gB1 = gB0 + (size_t)64 * KH2;
    const uint32_t dA0 = sb + (lr0 * SST + lc) * 4;
    const uint32_t dA1 = sb + ((lr0 + 64) * SST + lc) * 4;
    const uint32_t dB0 = sb + ((128 + lr0) * SST + lc) * 4;
    const uint32_t dB1 = sb + ((192 + lr0) * SST + lc) * 4;

    const uint32_t aoff = ((wr + (lane & 15)) * SST + ((lane >> 4) << 2)) * 4;
    const int lg = lane >> 3;
    const uint32_t boff = ((128 + wc + (lg & 2) * 4 + (lane & 7)) * SST + ((lg & 1) << 2)) * 4;

    float acc[4][4][4] = {};

#define PF(c) do { int k0 = (c) * 16; uint32_t bo = ((c) % NSTAGE) * (STG * 4); \
        CP16(dA0 + bo, gA0 + k0); CP16(dA1 + bo, gA1 + k0); \
        CP16(dB0 + bo, gB0 + k0); CP16(dB1 + bo, gB1 + k0); \
        CP_COMMIT(); } while (0)

    PF(0);
    PF(1);
#pragma unroll 1
    for (int c = 0; c < KITER; c++) {
        if (c == KITER - 1) { CP_WAIT0(); } else { CP_WAIT1(); }
        __syncthreads();
        if (c + NSTAGE - 1 < KITER) PF(c + NSTAGE - 1);
        const uint32_t Sb = sb + (c % NSTAGE) * (STG * 4);
#pragma unroll
        for (int ko = 0; ko < 16; ko += 8) {
            unsigned af[4][4];
#pragma unroll
            for (int mt = 0; mt < 4; mt++)
                ldsm_x4(af[mt], Sb + aoff + (mt * 16 * SST + ko) * 4);
#pragma unroll
            for (int nt2 = 0; nt2 < 2; nt2++) {
                unsigned bf[4];
                ldsm_x4(bf, Sb + boff + (nt2 * 16 * SST + ko) * 4);
#pragma unroll
                for (int mt = 0; mt < 4; mt++) {
                    mma_f16(acc[mt][2 * nt2],     af[mt], bf);
                    mma_f16(acc[mt][2 * nt2 + 1], af[mt], bf + 2);
                }
            }
        }
    }
#undef PF

    const int gp = lane >> 2, tg = lane & 3;
#pragma unroll
    for (int mt = 0; mt < 4; mt++)
#pragma unroll
        for (int nt = 0; nt < 4; nt++) {
            int row = bm + wr + mt * 16 + gp;
            int col = bn + wc + nt * 8 + 2 * tg;
            if (EPI_Y) {
                float* outf = (float*)Cout;
                float2 dv = *(const float2*)&Dv[col];
                float2 u0 = *(const float2*)&u[(size_t)row * H + col];
                float2 u1 = *(const float2*)&u[(size_t)(row + 8) * H + col];
                float2 o0 = make_float2(2.0f * acc[mt][nt][0] + u0.x * dv.x,
                                        2.0f * acc[mt][nt][1] + u0.y * dv.y);
                float2 o1 = make_float2(2.0f * acc[mt][nt][2] + u1.x * dv.x,
                                        2.0f * acc[mt][nt][3] + u1.y * dv.y);
                *(float2*)&outf[(size_t)row * ldc + col]       = o0;
                *(float2*)&outf[(size_t)(row + 8) * ldc + col] = o1;
            } else {
                __half* outh = (__half*)Cout;
                *(__half2*)&outh[(size_t)row * ldc + col] =
                    __floats2half2_rn(acc[mt][nt][0], acc[mt][nt][1]);
                *(__half2*)&outh[(size_t)(row + 8) * ldc + col] =
                    __floats2half2_rn(acc[mt][nt][2], acc[mt][nt][3]);
            }
        }
}

// ---------------- scan phase 1: per-chunk aggregates (half2, 2 ch/thread) ----
__global__ __launch_bounds__(128) void k_scan1(const unsigned int* __restrict__ start) {
    int c = blockIdx.x, q = threadIdx.x;     // q owns channels 2q, 2q+1
    int l0 = c * CHUNK;
    float2 Ar = *(const float2*)&g_Are[2 * q];
    float2 Ai = *(const float2*)&g_Aim[2 * q];
    float Mr0 = 1.0f, Mi0 = 0.0f, xr0 = 0.0f, xi0 = 0.0f;
    float Mr1 = 1.0f, Mi1 = 0.0f, xr1 = 0.0f, xi1 = 0.0f;
#pragma unroll 8
    for (int t = 0; t < CHUNK; t++) {
        int l = l0 + t;
        float2 br = __half22float2(*(const __half2*)&g_Bu_h[(size_t)l * 512 + 2 * q]);
        float2 bi = __half22float2(*(const __half2*)&g_Bu_h[(size_t)l * 512 + 256 + 2 * q]);
        bool s = (start[l] != 0u);
        float pr0 = s ? 0.0f : xr0, pi0 = s ? 0.0f : xi0;
        float mr0 = s ? 0.0f : Mr0, mi0 = s ? 0.0f : Mi0;
        float pr1 = s ? 0.0f : xr1, pi1 = s ? 0.0f : xi1;
        float mr1 = s ? 0.0f : Mr1, mi1 = s ? 0.0f : Mi1;
        xr0 = Ar.x * pr0 - Ai.x * pi0 + br.x;
        xi0 = Ar.x * pi0 + Ai.x * pr0 + bi.x;
        Mr0 = Ar.x * mr0 - Ai.x * mi0;
        Mi0 = Ar.x * mi0 + Ai.x * mr0;
        xr1 = Ar.y * pr1 - Ai.y * pi1 + br.y;
        xi1 = Ar.y * pi1 + Ai.y * pr1 + bi.y;
        Mr1 = Ar.y * mr1 - Ai.y * mi1;
        Mi1 = Ar.y * mi1 + Ai.y * mr1;
    }
    *(float2*)&g_Mre[c * P + 2 * q] = make_float2(Mr0, Mr1);
    *(float2*)&g_Mim[c * P + 2 * q] = make_float2(Mi0, Mi1);
    *(float2*)&g_bre[c * P + 2 * q] = make_float2(xr0, xr1);
    *(float2*)&g_bim[c * P + 2 * q] = make_float2(xi0, xi1);
}

// ---------------- scan phase 2a: group aggregates (8 chunks/group) -----------
__global__ __launch_bounds__(256) void k_scan2a() {
    int g = blockIdx.x, p = threadIdx.x;
    int c0 = g * CPG;
    float mr[CPG], mi[CPG], vr[CPG], vi[CPG];
#pragma unroll
    for (int j = 0; j < CPG; j++) {
        int a = (c0 + j) * P + p;
        mr[j] = g_Mre[a]; mi[j] = g_Mim[a]; vr[j] = g_bre[a]; vi[j] = g_bim[a];
    }
    float Mr = mr[0], Mi = mi[0], br = vr[0], bi = vi[0];
#pragma unroll
    for (int j = 1; j < CPG; j++) {
        float tMr = mr[j] * Mr - mi[j] * Mi;
        float tMi = mr[j] * Mi + mi[j] * Mr;
        float tbr = mr[j] * br - mi[j] * bi + vr[j];
        float tbi = mr[j] * bi + mi[j] * br + vi[j];
        Mr = tMr; Mi = tMi; br = tbr; bi = tbi;
    }
    g_gMr[g * P + p] = Mr; g_gMi[g * P + p] = Mi;
    g_gbr[g * P + p] = br; g_gbi[g * P + p] = bi;
}

// ---------------- scan phase 2b: serial prefix over NG groups (depth-8 PF) ---
__global__ __launch_bounds__(256) void k_scan2b(const float* __restrict__ hidden) {
    int p = threadIdx.x;
    float bmr[8], bmi[8], bvr[8], bvi[8];
#pragma unroll
    for (int k = 0; k < 8; k++) {
        int a = k * P + p;
        bmr[k] = g_gMr[a]; bmi[k] = g_gMi[a]; bvr[k] = g_gbr[a]; bvi[k] = g_gbi[a];
    }
    float xr = hidden[p], xi = 0.0f;
#pragma unroll
    for (int g = 0; g < NG; g++) {
        int s = g & 7;
        float mr = bmr[s], mi = bmi[s], vr = bvr[s], vi = bvi[s];
        if (g + 8 < NG) {
            int a = (g + 8) * P + p;
            bmr[s] = g_gMr[a]; bmi[s] = g_gMi[a]; bvr[s] = g_gbr[a]; bvi[s] = g_gbi[a];
        }
        g_xgr[g * P + p] = xr; g_xgi[g * P + p] = xi;
        float nr = mr * xr - mi * xi + vr;
        float ni = mr * xi + mi * xr + vi;
        xr = nr; xi = ni;
    }
}

// ---------------- scan phase 2c: expand group prefixes to chunk prefixes -----
__global__ __launch_bounds__(256) void k_scan2c() {
    int g = blockIdx.x, p = threadIdx.x;
    int c0 = g * CPG;
    float mr[CPG], mi[CPG], vr[CPG], vi[CPG];
#pragma unroll
    for (int j = 0; j < CPG; j++) {
        int a = (c0 + j) * P + p;
        mr[j] = g_Mre[a]; mi[j] = g_Mim[a]; vr[j] = g_bre[a]; vi[j] = g_bim[a];
    }
    float xr = g_xgr[g * P + p], xi = g_xgi[g * P + p];
#pragma unroll
    for (int j = 0; j < CPG; j++) {
        g_x0re[(c0 + j) * P + p] = xr;
        g_x0im[(c0 + j) * P + p] = xi;
        float nr = mr[j] * xr - mi[j] * xi + vr[j];
        float ni = mr[j] * xi + mi[j] * xr + vi[j];
        xr = nr; xi = ni;
    }
}

// ---------------- scan phase 3: re-scan (half2, 2 ch/thread), write xs -------
__global__ __launch_bounds__(128) void k_scan3(const unsigned int* __restrict__ start,
                                               float* __restrict__ out, int fmt) {
    int c = blockIdx.x, q = threadIdx.x;     // q owns channels 2q, 2q+1
    float2 Ar = *(const float2*)&g_Are[2 * q];
    float2 Ai = *(const float2*)&g_Aim[2 * q];
    float2 x0r = *(const float2*)&g_x0re[c * P + 2 * q];
    float2 x0i = *(const float2*)&g_x0im[c * P + 2 * q];
    float xr0 = x0r.x, xi0 = x0i.x, xr1 = x0r.y, xi1 = x0i.y;
    int l0 = c * CHUNK;
    __half2* xs = (__half2*)g_xs_h;
#pragma unroll 8
    for (int t = 0; t < CHUNK; t++) {
        int l = l0 + t;
        float2 br = __half22float2(*(const __half2*)&g_Bu_h[(size_t)l * 512 + 2 * q]);
        float2 bi = __half22float2(*(const __half2*)&g_Bu_h[(size_t)l * 512 + 256 + 2 * q]);
        bool s = (start[l] != 0u);
        float pr0 = s ? 0.0f : xr0, pi0 = s ? 0.0f : xi0;
        float pr1 = s ? 0.0f : xr1, pi1 = s ? 0.0f : xi1;
        xr0 = Ar.x * pr0 - Ai.x * pi0 + br.x;
        xi0 = Ar.x * pi0 + Ai.x * pr0 + bi.x;
        xr1 = Ar.y * pr1 - Ai.y * pi1 + br.y;
        xi1 = Ar.y * pi1 + Ai.y * pr1 + bi.y;
        xs[(size_t)l * 256 + q]       = __floats2half2_rn(xr0, xr1);
        xs[(size_t)l * 256 + 128 + q] = __floats2half2_rn(xi0, xi1);
    }
    if (c == NC - 1) {
        if (fmt == 2) {
            out[4 * q]     = xr0; out[4 * q + 1] = xi0;
            out[4 * q + 2] = xr1; out[4 * q + 3] = xi1;
        } else if (fmt == 1) {
            out[2 * q] = xr0; out[2 * q + 1] = xr1;
        }
    }
}

// ---------------- launcher ---------------------------------------------------
extern "C" void kernel_launch(void* const* d_in, const int* in_sizes, int n_in,
                              void* d_out, int out_size) {
    const float* Lre    = (const float*)d_in[0];
    const float* Lim    = (const float*)d_in[1];
    const float* Bin    = (const float*)d_in[2];
    const float* Cin    = (const float*)d_in[3];
    const float* lstep  = (const float*)d_in[4];
    const float* D      = (const float*)d_in[5];
    const float* hidden = (const float*)d_in[6];
    const float* u      = (const float*)d_in[7];
    const unsigned int* start = (const unsigned int*)d_in[8];
    float* out = (float*)d_out;

    int state_floats = out_size - L * H;
    if (state_floats < 0) state_floats = 0;
    int fmt = (state_floats >= 2 * P) ? 2 : (state_floats >= P ? 1 : 0);
    float* ys = out + state_floats;

    cudaFuncSetAttribute(k_gemm<128, false>, cudaFuncAttributeMaxDynamicSharedMemorySize, GSMEM);
    cudaFuncSetAttribute(k_gemm<256, true>,  cudaFuncAttributeMaxDynamicSharedMemorySize, GSMEM);

    int prep_blocks = (NU + NDC + NSU + 255) / 256;
    k_prep<<<prep_blocks, 256>>>(u, Cin, Lre, Lim, Bin, lstep);

    // GEMM1: Bu_h[l, 0:512] = u @ [Bre; Bim]^T   (K = 256 halves = 128 uints)
    {
        void *bu_dev = nullptr, *a_dev = nullptr, *b_dev = nullptr;
        cudaGetSymbolAddress(&bu_dev, g_Bu_h);
        cudaGetSymbolAddress(&a_dev, g_u_h);
        cudaGetSymbolAddress(&b_dev, g_Bcat);
        dim3 g(L / 128, 512 / 128);
        k_gemm<128, false><<<g, 256, GSMEM>>>((const unsigned*)a_dev, (const unsigned*)b_dev,
                                              bu_dev, 512, nullptr, nullptr);
    }

    k_scan1<<<NC, 128>>>(start);
    k_scan2a<<<NG, P>>>();
    k_scan2b<<<1, P>>>(hidden);
    k_scan2c<<<NG, P>>>();
    k_scan3<<<NC, 128>>>(start, out, fmt);

    // GEMM2: ys = 2 * (xs_cat @ Ccat^T) + u * D   (K = 512 halves = 256 uints)
    {
        void *a_dev = nullptr, *b_dev = nullptr;
        cudaGetSymbolAddress(&a_dev, g_xs_h);
        cudaGetSymbolAddress(&b_dev, g_Ccat);
        dim3 g(L / 128, H / 128);
        k_gemm<256, true><<<g, 256, GSMEM>>>((const unsigned*)a_dev, (const unsigned*)b_dev,
                                             ys, H, u, D);
    }
}